// round 8
// baseline (speedup 1.0000x reference)
#include <cuda_runtime.h>

#define NX 8192
#define NY 8192
#define ROWS 16
#define TPB 256
#define JPT 4   // columns per thread (two f32x2 pairs)

typedef unsigned long long u64;

// Precomputed trig (no cudaMalloc allowed -> device globals)
__device__ float g_cx20[NX];   // 20*cos(pi*x)
__device__ float g_sx20[NX];   // 20*sin(pi*x)
__device__ float g_cy[NY];     // cos(pi*y)
__device__ float g_sy[NY];     // sin(pi*y)

__global__ void precompute_kernel(const float* __restrict__ x,
                                  const float* __restrict__ y) {
    int i = blockIdx.x * blockDim.x + threadIdx.x;
    float s, c;
    sincospif(x[i], &s, &c);
    g_cx20[i] = 20.0f * c;
    g_sx20[i] = 20.0f * s;
    sincospif(y[i], &s, &c);
    g_cy[i] = c;
    g_sy[i] = s;
}

// ---- packed f32x2 helpers ----
// pack/unpack via union: compiler-visible register-pair aliasing (no forced MOVs)
union F2U { u64 u; float2 f; };
__device__ __forceinline__ float2 upk2(u64 v) { F2U t; t.u = v; return t.f; }
__device__ __forceinline__ u64 pk2f(float lo, float hi) {
    F2U t; t.f.x = lo; t.f.y = hi; return t.u;
}
__device__ __forceinline__ u64 fma2_(u64 a, u64 b, u64 c) {
    u64 d; asm("fma.rn.f32x2 %0, %1, %2, %3;" : "=l"(d) : "l"(a), "l"(b), "l"(c)); return d;
}
__device__ __forceinline__ u64 mul2_(u64 a, u64 b) {
    u64 d; asm("mul.rn.f32x2 %0, %1, %2;" : "=l"(d) : "l"(a), "l"(b)); return d;
}
__device__ __forceinline__ float ex2_(float a) {
    float r; asm("ex2.approx.f32 %0, %1;" : "=f"(r) : "f"(a)); return r;
}
// Compiler-visible packed constant (ptxas can uniform-promote)
__device__ __forceinline__ u64 rep2(float f) {
    unsigned u = __float_as_uint(f);
    return ((u64)u << 32) | (u64)u;
}

// K = exp(-20) * I0(z),  z = 20*cos(pi*(x-y)) = cx20*cy + sx20*sy,  t=|z|<=20
// Single path (global-norm error metric; small-t values are <=1e-6 of peak):
//   tc = max(|z|, 5.0)
//   result = p2(1/tc) * rsqrt(tc) * exp2(|z|*log2e - 20*log2e)
// p2 = truncated asymptotic series of i0e(t)*sqrt(t) (exact coefficients):
//   (1/sqrt(2pi)) * (1 + w/8 + 9w^2/128),  w = 1/tc in [0.05, 0.2].
// __launch_bounds__(TPB, 8): force 32-reg allocation -> 8 CTAs/SM (64 warps).
// R7 let regs drift to 35 (alloc 40) which cost 25% occupancy.
__global__ __launch_bounds__(TPB, 8) void bessel_kernel(float* __restrict__ out) {
    __shared__ u64 scx[ROWS];
    __shared__ u64 ssx[ROWS];

    const int tid = threadIdx.x;
    const int j0 = blockIdx.x * (TPB * JPT) + tid * JPT;
    const int r0 = blockIdx.y * ROWS;

    if (tid < ROWS) {
        float c = g_cx20[r0 + tid];
        float s = g_sx20[r0 + tid];
        scx[tid] = pk2f(c, c);   // replicated pair -> single LDS.64 in the loop
        ssx[tid] = pk2f(s, s);
    }
    __syncthreads();

    const float4 cy4 = *reinterpret_cast<const float4*>(&g_cy[j0]);
    const float4 sy4 = *reinterpret_cast<const float4*>(&g_sy[j0]);
    const u64 cyA = pk2f(cy4.x, cy4.y), cyB = pk2f(cy4.z, cy4.w);
    const u64 syA = pk2f(sy4.x, sy4.y), syB = pk2f(sy4.z, sy4.w);

    // asymptotic-series coeffs (exact), pre-multiplied by 1/sqrt(2*pi)
    const u64 cC2 = rep2(0.02805078f);    // 9/128 / sqrt(2pi)
    const u64 cC1 = rep2(0.04986779f);    // 1/8   / sqrt(2pi)
    const u64 cC0 = rep2(0.39894228f);    // 1/sqrt(2pi)
    // scalar exp2-arg constants (FFMA-imm form: rt=1 on fma pipe)
    const float L2E = 1.4426950f;         // log2(e)
    const float M20 = -28.8539009f;       // -20*log2(e)

    float* orow = out + (size_t)r0 * NY + j0;

    #pragma unroll
    for (int r = 0; r < ROWS; ++r) {
        const u64 cx2 = scx[r];
        const u64 sx2 = ssx[r];
        float4 res;

        // -------- pair A (columns j0, j0+1) --------
        {
            u64 z = fma2_(cx2, cyA, mul2_(sx2, syA));
            float2 zf = upk2(z);
            float tcx = fmaxf(fabsf(zf.x), 5.0f);     // FMNMX with free |mod|
            float tcy = fmaxf(fabsf(zf.y), 5.0f);
            u64 rs = pk2f(rsqrtf(tcx), rsqrtf(tcy));
            u64 w = mul2_(rs, rs);
            u64 pl = fma2_(w, cC2, cC1);
            pl = fma2_(w, pl, cC0);
            pl = mul2_(pl, rs);
            float argx = fmaf(fabsf(zf.x), L2E, M20); // FFMA-imm, free |mod|
            float argy = fmaf(fabsf(zf.y), L2E, M20);
            float2 plf = upk2(pl);
            res.x = plf.x * ex2_(argx);
            res.y = plf.y * ex2_(argy);
        }

        // -------- pair B (columns j0+2, j0+3) --------
        {
            u64 z = fma2_(cx2, cyB, mul2_(sx2, syB));
            float2 zf = upk2(z);
            float tcx = fmaxf(fabsf(zf.x), 5.0f);
            float tcy = fmaxf(fabsf(zf.y), 5.0f);
            u64 rs = pk2f(rsqrtf(tcx), rsqrtf(tcy));
            u64 w = mul2_(rs, rs);
            u64 pl = fma2_(w, cC2, cC1);
            pl = fma2_(w, pl, cC0);
            pl = mul2_(pl, rs);
            float argx = fmaf(fabsf(zf.x), L2E, M20);
            float argy = fmaf(fabsf(zf.y), L2E, M20);
            float2 plf = upk2(pl);
            res.z = plf.x * ex2_(argx);
            res.w = plf.y * ex2_(argy);
        }

        // write-once data: streaming store (evict-first) to ease L2 dirty pressure
        __stcs(reinterpret_cast<float4*>(orow), res);
        orow += NY;
    }
}

extern "C" void kernel_launch(void* const* d_in, const int* in_sizes, int n_in,
                              void* d_out, int out_size) {
    const float* x = (const float*)d_in[0];
    const float* y = (const float*)d_in[1];
    float* out = (float*)d_out;

    precompute_kernel<<<NX / TPB, TPB>>>(x, y);

    dim3 grid(NY / (TPB * JPT), NX / ROWS);
    bessel_kernel<<<grid, TPB>>>(out);
}

// round 9
// speedup vs baseline: 1.0163x; 1.0163x over previous
#include <cuda_runtime.h>

#define NX 8192
#define NY 8192
#define ROWS 16
#define TPB 256
#define JPT 4   // columns per thread (two f32x2 pairs for z; scalar after)

typedef unsigned long long u64;

// Precomputed trig (no cudaMalloc allowed -> device globals)
__device__ float g_cx20[NX];   // 20*cos(pi*x)
__device__ float g_sx20[NX];   // 20*sin(pi*x)
__device__ float g_cy[NY];     // cos(pi*y)
__device__ float g_sy[NY];     // sin(pi*y)

__global__ void precompute_kernel(const float* __restrict__ x,
                                  const float* __restrict__ y) {
    int i = blockIdx.x * blockDim.x + threadIdx.x;
    float s, c;
    sincospif(x[i], &s, &c);
    g_cx20[i] = 20.0f * c;
    g_sx20[i] = 20.0f * s;
    sincospif(y[i], &s, &c);
    g_cy[i] = c;
    g_sy[i] = s;
}

// ---- minimal packed helpers (z dot-product only) ----
union F2U { u64 u; float2 f; };
__device__ __forceinline__ float2 upk2(u64 v) { F2U t; t.u = v; return t.f; }
__device__ __forceinline__ u64 pk2f(float lo, float hi) {
    F2U t; t.f.x = lo; t.f.y = hi; return t.u;
}
__device__ __forceinline__ u64 fma2_(u64 a, u64 b, u64 c) {
    u64 d; asm("fma.rn.f32x2 %0, %1, %2, %3;" : "=l"(d) : "l"(a), "l"(b), "l"(c)); return d;
}
__device__ __forceinline__ u64 mul2_(u64 a, u64 b) {
    u64 d; asm("mul.rn.f32x2 %0, %1, %2;" : "=l"(d) : "l"(a), "l"(b)); return d;
}
__device__ __forceinline__ float ex2_(float a) {
    float r; asm("ex2.approx.f32 %0, %1;" : "=f"(r) : "f"(a)); return r;
}

// K = exp(-20) * I0(z),  z = 20*cos(pi*(x-y)) = cx20*cy + sx20*sy,  t=|z|<=20
// Single path (global-norm error metric; small-t values are <=1e-6 of peak):
//   tc = max(|z|, 5.0)
//   result = p2(1/tc) * rsqrt(tc) * exp2(|z|*log2e - 20*log2e)
// p2 = truncated asymptotic series of i0e(t)*sqrt(t) (exact coefficients):
//   (1/sqrt(2pi)) * (1 + w/8 + 9w^2/128),  w = 1/tc in [0.05, 0.2].
//
// ALL math after z is SCALAR: float-literal constants fold into FFMA-imm /
// FMUL-imm (rt=1) with no register-pair alignment MOVs. R8's SASS carried
// ~5.7 bogus slots/elem of MOV32I+pair-shuffle from packed u64 constants
// (no cbank operands on Blackwell).
__device__ __forceinline__ float bessel_tail(float zv) {
    float t  = fabsf(zv);
    float tc = fmaxf(t, 5.0f);                  // FMNMX (|mod| free)
    float rs = rsqrtf(tc);                      // MUFU.RSQ
    float w  = rs * rs;
    float p  = fmaf(w, 0.02805078f, 0.04986779f);   // 9/128/sqrt(2pi), 1/8/sqrt(2pi)
    p = fmaf(w, p, 0.39894228f);                    // 1/sqrt(2pi)
    float arg = fmaf(t, 1.4426950f, -28.8539009f);  // t*log2e - 20*log2e
    return p * rs * ex2_(arg);                  // MUFU.EX2
}

__global__ __launch_bounds__(TPB, 8) void bessel_kernel(float* __restrict__ out) {
    __shared__ u64 scx[ROWS];
    __shared__ u64 ssx[ROWS];

    const int tid = threadIdx.x;
    const int j0 = blockIdx.x * (TPB * JPT) + tid * JPT;
    const int r0 = blockIdx.y * ROWS;

    if (tid < ROWS) {
        float c = g_cx20[r0 + tid];
        float s = g_sx20[r0 + tid];
        scx[tid] = pk2f(c, c);   // replicated pair -> single LDS.64 in the loop
        ssx[tid] = pk2f(s, s);
    }
    __syncthreads();

    const float4 cy4 = *reinterpret_cast<const float4*>(&g_cy[j0]);
    const float4 sy4 = *reinterpret_cast<const float4*>(&g_sy[j0]);
    const u64 cyA = pk2f(cy4.x, cy4.y), cyB = pk2f(cy4.z, cy4.w);
    const u64 syA = pk2f(sy4.x, sy4.y), syB = pk2f(sy4.z, sy4.w);

    float* orow = out + (size_t)r0 * NY + j0;

    #pragma unroll
    for (int r = 0; r < ROWS; ++r) {
        const u64 cx2 = scx[r];
        const u64 sx2 = ssx[r];

        // packed dot-products for z (only place f32x2 pays off)
        u64 zA = fma2_(cx2, cyA, mul2_(sx2, syA));
        u64 zB = fma2_(cx2, cyB, mul2_(sx2, syB));
        float2 zfA = upk2(zA);
        float2 zfB = upk2(zB);

        float4 res;
        res.x = bessel_tail(zfA.x);
        res.y = bessel_tail(zfA.y);
        res.z = bessel_tail(zfB.x);
        res.w = bessel_tail(zfB.y);

        // write-once data: streaming store (evict-first)
        __stcs(reinterpret_cast<float4*>(orow), res);
        orow += NY;
    }
}

extern "C" void kernel_launch(void* const* d_in, const int* in_sizes, int n_in,
                              void* d_out, int out_size) {
    const float* x = (const float*)d_in[0];
    const float* y = (const float*)d_in[1];
    float* out = (float*)d_out;

    precompute_kernel<<<NX / TPB, TPB>>>(x, y);

    dim3 grid(NY / (TPB * JPT), NX / ROWS);
    bessel_kernel<<<grid, TPB>>>(out);
}